// round 8
// baseline (speedup 1.0000x reference)
#include <cuda_runtime.h>
#include <cstdint>

// ---------------------------------------------------------------------------
// MambaBlock: rmsnorm -> [gate|p] GEMM (tf32 mma.sync) -> chunked scan -> out GEMM
// Shapes: B=4, S=4096, D=1024, H=16, Dstate=64
// NOTE: harness PTX target is compute_103 (no 'a') -> tcgen05 unavailable;
//       legacy mma.sync tf32 is the fastest usable tensor path.
// ---------------------------------------------------------------------------

#define MAX_M 16384
#define NCH   4096
#define CHUNKS 64

// device-global scratch (no allocation allowed)
__device__ float g_xn[(size_t)MAX_M * 1024];     // xn (tf32-rounded), later "mixed"
__device__ float g_proj[(size_t)MAX_M * 4096];   // [gate(1024) | p(3072)] per token
__device__ float g_wg[(size_t)1024 * 1024];      // tf32-rounded Wg  [K,N]
__device__ float g_wp[(size_t)1024 * 3072];      // tf32-rounded Wp  [K,N]
__device__ float g_wo[(size_t)1024 * 1024];      // tf32-rounded Wo  [K,N]
__device__ float g_cA[NCH * CHUNKS];
__device__ float g_cB[NCH * CHUNKS];
__device__ float g_hin[NCH * CHUNKS];

// ---------------------------------------------------------------------------
__device__ __forceinline__ uint32_t f2tf32(float x) {
    uint32_t r;
    asm("cvt.rna.tf32.f32 %0, %1;" : "=r"(r) : "f"(x));
    return r;
}
__device__ __forceinline__ void mma8(float* c,
                                     uint32_t a0, uint32_t a1, uint32_t a2, uint32_t a3,
                                     uint32_t b0, uint32_t b1) {
    asm volatile(
        "mma.sync.aligned.m16n8k8.row.col.f32.tf32.tf32.f32 "
        "{%0,%1,%2,%3},{%4,%5,%6,%7},{%8,%9},{%0,%1,%2,%3};"
        : "+f"(c[0]), "+f"(c[1]), "+f"(c[2]), "+f"(c[3])
        : "r"(a0), "r"(a1), "r"(a2), "r"(a3), "r"(b0), "r"(b1));
}
__device__ __forceinline__ void cpasync16(uint32_t saddr, const void* g) {
    asm volatile("cp.async.cg.shared.global [%0], [%1], 16;" :: "r"(saddr), "l"(g));
}
__device__ __forceinline__ float sigmoidf_(float v) {
    return 1.0f / (1.0f + __expf(-v));
}

// ---------------------------------------------------------------------------
// Pre-round all weights to tf32.
__global__ void round_weights_kernel(const float* __restrict__ Wg,
                                     const float* __restrict__ Wp,
                                     const float* __restrict__ Wo) {
    const int i = blockIdx.x * blockDim.x + threadIdx.x;  // float4 index
    const int NG = 256 * 1024;
    const int NP = 768 * 1024;
    const float4* src;
    float4* dst;
    int j;
    if (i < NG)            { src = (const float4*)Wg; dst = (float4*)g_wg; j = i; }
    else if (i < NG + NP)  { src = (const float4*)Wp; dst = (float4*)g_wp; j = i - NG; }
    else                   { src = (const float4*)Wo; dst = (float4*)g_wo; j = i - NG - NP; }
    float4 v = src[j];
    v.x = __uint_as_float(f2tf32(v.x));
    v.y = __uint_as_float(f2tf32(v.y));
    v.z = __uint_as_float(f2tf32(v.z));
    v.w = __uint_as_float(f2tf32(v.w));
    dst[j] = v;
}

// ---------------------------------------------------------------------------
// RMSNorm -> tf32-rounded xn
__global__ void rmsnorm_kernel(const float* __restrict__ x, const float* __restrict__ w) {
    const int row = blockIdx.x;
    const int tid = threadIdx.x;
    const float4* xr = (const float4*)(x + (size_t)row * 1024);
    float4 v = xr[tid];
    float ss = v.x * v.x + v.y * v.y + v.z * v.z + v.w * v.w;
    #pragma unroll
    for (int o = 16; o; o >>= 1) ss += __shfl_xor_sync(0xffffffff, ss, o);
    __shared__ float sred[8];
    const int lane = tid & 31, warp = tid >> 5;
    if (lane == 0) sred[warp] = ss;
    __syncthreads();
    if (warp == 0) {
        float t = sred[lane & 7];
        #pragma unroll
        for (int o = 4; o; o >>= 1) t += __shfl_xor_sync(0xffffffff, t, o);
        if (lane == 0) sred[0] = t;
    }
    __syncthreads();
    const float rinv = rsqrtf(sred[0] * (1.0f / 1024.0f) + 1e-6f);
    const float4 wv = ((const float4*)w)[tid];
    float4 o;
    o.x = __uint_as_float(f2tf32(v.x * rinv * wv.x));
    o.y = __uint_as_float(f2tf32(v.y * rinv * wv.y));
    o.z = __uint_as_float(f2tf32(v.z * rinv * wv.z));
    o.w = __uint_as_float(f2tf32(v.w * rinv * wv.w));
    ((float4*)(g_xn + (size_t)row * 1024))[tid] = o;
}

// ---------------------------------------------------------------------------
// TF32 GEMM: CTA tile 256(M) x 128(N), BK=16, 256 threads.
// Warps 4(m) x 2(n), warp tile 64x64 -> per k8: 32 mma / 32 LDS (50% mma mix).
// 3-stage cp.async pipeline, wait_group 1 (2 load groups in flight).
constexpr int ASTR = 20;                 // A smem row stride (16+4)
constexpr int BSTR = 136;                // B smem row stride (128+8)
constexpr int ASTAGE = 256 * ASTR;       // floats per A stage (5120)
constexpr int BSTAGE = 16 * BSTR;        // floats per B stage (2176)
constexpr int GSMEM_BYTES = 3 * (ASTAGE + BSTAGE) * 4;  // 87552

template<int EPI>
__global__ __launch_bounds__(256, 1)
void gemm_tf32(const float* __restrict__ bias0, const float* __restrict__ bias1,
               const float* __restrict__ resid, float* __restrict__ outp, int M) {
    extern __shared__ float smem[];
    float* Asm = smem;                    // 3 stages
    float* Bsm = smem + 3 * ASTAGE;       // 3 stages

    const int tid  = threadIdx.x;
    const int lane = tid & 31, warp = tid >> 5;
    const int wm = warp & 3, wn = warp >> 2;      // 4 x 2 warps
    const int bm = blockIdx.y, bn = blockIdx.x;

    const float* Bmat;
    int ldb, bcol, ldo;
    bool isGate;
    float* out;
    if (EPI == 1) {
        ldo = 4096;
        out = g_proj;
        isGate = (bn * 128 < 1024);
        if (isGate) { Bmat = g_wg; ldb = 1024; bcol = bn * 128; }
        else        { Bmat = g_wp; ldb = 3072; bcol = bn * 128 - 1024; }
    } else {
        ldo = 1024; isGate = false;
        out = outp;
        Bmat = g_wo; ldb = 1024; bcol = bn * 128;
    }

    // loader indices: A 256x16 (1024 f4, 4/thread), B 16x128 (512 f4, 2/thread)
    const int arow = tid >> 2;     // 0..63 (+64,+128,+192)
    const int ac4  = tid & 3;
    const int brow = tid >> 5;     // 0..7 (+8)
    const int bc4  = tid & 31;

    const float* gA = g_xn + (size_t)(bm * 256 + arow) * 1024 + ac4 * 4;
    const float* gB = Bmat + (size_t)brow * ldb + bcol + bc4 * 4;

    const uint32_t sA = (uint32_t)__cvta_generic_to_shared(Asm);
    const uint32_t sB = (uint32_t)__cvta_generic_to_shared(Bsm);

    float c[4][8][4];
    #pragma unroll
    for (int i = 0; i < 4; i++)
        #pragma unroll
        for (int j = 0; j < 8; j++)
            #pragma unroll
            for (int k = 0; k < 4; k++) c[i][j][k] = 0.0f;

    const int KT = 64;   // 1024 / 16

    #define LOAD_STAGE(s)                                                         \
    {                                                                             \
        const int _buf = (s) % 3;                                                 \
        const int _kb  = (s) * 16;                                                \
        _Pragma("unroll")                                                         \
        for (int _j = 0; _j < 4; _j++)                                            \
            cpasync16(sA + (_buf * ASTAGE + (arow + 64 * _j) * ASTR + ac4 * 4) * 4, \
                      gA + _kb + (size_t)(64 * _j) * 1024);                       \
        _Pragma("unroll")                                                         \
        for (int _j = 0; _j < 2; _j++)                                            \
            cpasync16(sB + (_buf * BSTAGE + (brow + 8 * _j) * BSTR + bc4 * 4) * 4, \
                      gB + ((size_t)_kb + 8 * _j) * ldb);                         \
        asm volatile("cp.async.commit_group;");                                   \
    }

    LOAD_STAGE(0)
    LOAD_STAGE(1)

    for (int kt = 0; kt < KT; kt++) {
        asm volatile("cp.async.wait_group 1;");
        __syncthreads();

        if (kt + 2 < KT) LOAD_STAGE(kt + 2)

        const float* Ab = Asm + (kt % 3) * ASTAGE;
        const float* Bb = Bsm + (kt % 3) * BSTAGE;

        #pragma unroll
        for (int ks = 0; ks < 2; ks++) {
            uint32_t af[4][4], bf[8][2];
            const int r0 = wm * 64 + (lane >> 2);
            const int cc = ks * 8 + (lane & 3);
            #pragma unroll
            for (int mt = 0; mt < 4; mt++) {
                const float* ap = Ab + (r0 + mt * 16) * ASTR + cc;
                af[mt][0] = __float_as_uint(ap[0]);
                af[mt][1] = __float_as_uint(ap[8 * ASTR]);
                af[mt][2] = __float_as_uint(ap[4]);
                af[mt][3] = __float_as_uint(ap[8 * ASTR + 4]);
            }
            const int kr  = ks * 8 + (lane & 3);
            const int nb0 = wn * 64 + (lane >> 2);
            #pragma unroll
            for (int nt = 0; nt < 8; nt++) {
                const float* bp2 = Bb + kr * BSTR + nb0 + nt * 8;
                bf[nt][0] = __float_as_uint(bp2[0]);
                bf[nt][1] = __float_as_uint(bp2[4 * BSTR]);
            }
            #pragma unroll
            for (int mt = 0; mt < 4; mt++)
                #pragma unroll
                for (int nt = 0; nt < 8; nt++)
                    mma8(c[mt][nt], af[mt][0], af[mt][1], af[mt][2], af[mt][3],
                         bf[nt][0], bf[nt][1]);
        }
    }
    #undef LOAD_STAGE

    // epilogue
    #pragma unroll
    for (int mt = 0; mt < 4; mt++) {
        const int rbase = bm * 256 + wm * 64 + mt * 16 + (lane >> 2);
        #pragma unroll
        for (int nt = 0; nt < 8; nt++) {
            const int col0 = bn * 128 + wn * 64 + nt * 8 + (lane & 3) * 2;
            float b0v, b1v;
            bool sg;
            if (EPI == 1) {
                if (isGate) { b0v = bias0[col0]; b1v = bias0[col0 + 1]; sg = true; }
                else {
                    b0v = bias1[col0 - 1024]; b1v = bias1[col0 - 1023];
                    sg = (((col0 - 1024) % 192) < 64);   // delta columns
                }
            } else {
                b0v = bias0[col0]; b1v = bias0[col0 + 1]; sg = false;
            }
            #pragma unroll
            for (int half = 0; half < 2; half++) {
                const int row = rbase + 8 * half;
                float v0 = c[mt][nt][2 * half]     + b0v;
                float v1 = c[mt][nt][2 * half + 1] + b1v;
                if (EPI == 2) {
                    const float2 rr = *(const float2*)(resid + (size_t)row * 1024 + col0);
                    v0 += rr.x; v1 += rr.y;
                } else if (sg) {
                    v0 = sigmoidf_(v0); v1 = sigmoidf_(v1);
                }
                float2 st; st.x = v0; st.y = v1;
                *(float2*)(out + (size_t)row * ldo + col0) = st;
            }
        }
    }
}

// ---------------------------------------------------------------------------
// Chunked parallel scan (verified 5 TB/s class in round 6)
__global__ __launch_bounds__(256) void scan_pass1(int S, int L) {
    const int gid = blockIdx.x * blockDim.x + threadIdx.x;
    const int t = gid & (NCH - 1);
    const int c = gid >> 12;
    const int b  = t >> 10;
    const int hd = t & 1023;
    const int hh = hd >> 6;
    const int d  = hd & 63;
    const float* __restrict__ pd = g_proj + (size_t)b * S * 4096 + 1024 + hh * 192 + d
                                   + (size_t)c * L * 4096;
    float A = 1.0f, h = 0.0f;
    #pragma unroll 8
    for (int s = 0; s < L; s++) {
        const float dl = pd[(size_t)s * 4096];
        const float bv = pd[(size_t)s * 4096 + 64];
        A *= dl;
        h = fmaf(dl, h, bv);
    }
    g_cA[gid] = A;
    g_cB[gid] = h;
}

__global__ __launch_bounds__(256) void scan_pass2(const float* __restrict__ state0,
                                                  float* __restrict__ state_out, int C) {
    const int t = blockIdx.x * blockDim.x + threadIdx.x;
    float h = state0[t];
    #pragma unroll 8
    for (int c = 0; c < C; c++) {
        g_hin[c * NCH + t] = h;
        h = fmaf(g_cA[c * NCH + t], h, g_cB[c * NCH + t]);
    }
    if (state_out) state_out[t] = h;
}

__global__ __launch_bounds__(256) void scan_pass3(int S, int L) {
    const int gid = blockIdx.x * blockDim.x + threadIdx.x;
    const int t = gid & (NCH - 1);
    const int c = gid >> 12;
    const int b  = t >> 10;
    const int hd = t & 1023;
    const int hh = hd >> 6;
    const int d  = hd & 63;
    const size_t base = (size_t)b * S * 4096 + (size_t)c * L * 4096;
    const float* __restrict__ pd = g_proj + base + 1024 + hh * 192 + d;
    const float* __restrict__ pg = g_proj + base + hd;
    float* __restrict__ xr = g_xn + (size_t)b * S * 1024 + hd + (size_t)c * L * 1024;
    float h = g_hin[gid];
    #pragma unroll 4
    for (int s = 0; s < L; s++) {
        const float dl = pd[(size_t)s * 4096];
        const float bv = pd[(size_t)s * 4096 + 64];
        const float cv = pd[(size_t)s * 4096 + 128];
        const float g  = pg[(size_t)s * 4096];
        h = fmaf(dl, h, bv);
        const float ssm = cv * h;
        const float xv  = xr[(size_t)s * 1024];
        xr[(size_t)s * 1024] = __uint_as_float(f2tf32(fmaf(g, ssm - xv, xv)));
    }
}

// ---------------------------------------------------------------------------
extern "C" void kernel_launch(void* const* d_in, const int* in_sizes, int n_in,
                              void* d_out, int out_size) {
    const float* x      = (const float*)d_in[0];
    const float* state  = (const float*)d_in[1];
    const float* norm_w = (const float*)d_in[2];
    const float* Wp     = (const float*)d_in[3];
    const float* bp     = (const float*)d_in[4];
    const float* Wg     = (const float*)d_in[5];
    const float* bg     = (const float*)d_in[6];
    const float* Wo     = (const float*)d_in[7];
    const float* bo     = (const float*)d_in[8];
    float* out = (float*)d_out;

    const int M = in_sizes[0] / 1024;  // 16384
    const int S = M / 4;               // 4096
    const int L = S / CHUNKS;          // 64

    // idempotent attribute set (no static guards; not a stream op)
    cudaFuncSetAttribute(gemm_tf32<1>, cudaFuncAttributeMaxDynamicSharedMemorySize,
                         GSMEM_BYTES);
    cudaFuncSetAttribute(gemm_tf32<2>, cudaFuncAttributeMaxDynamicSharedMemorySize,
                         GSMEM_BYTES);

    round_weights_kernel<<<(5 * 256 * 1024 + 255) / 256, 256>>>(Wg, Wp, Wo);
    rmsnorm_kernel<<<M, 256>>>(x, norm_w);

    gemm_tf32<1><<<dim3(32, M / 256), 256, GSMEM_BYTES>>>(bg, bp, nullptr, nullptr, M);

    float* state_out = nullptr;
    if (out_size >= M * 1024 + 4096) state_out = out + (size_t)M * 1024;
    scan_pass1<<<NCH * CHUNKS / 256, 256>>>(S, L);
    scan_pass2<<<NCH / 256, 256>>>(state, state_out, CHUNKS);
    scan_pass3<<<NCH * CHUNKS / 256, 256>>>(S, L);

    gemm_tf32<2><<<dim3(8, M / 256), 256, GSMEM_BYTES>>>(bo, nullptr, x, out, M);
}

// round 14
// speedup vs baseline: 1.8236x; 1.8236x over previous
#include <cuda_runtime.h>
#include <cuda_fp16.h>
#include <cstdint>

// ---------------------------------------------------------------------------
// MambaBlock: rmsnorm -> [gate|p] GEMM (fp16 mma.sync m16n8k16) -> chunked scan
//             -> out GEMM.  Shapes: B=4, S=4096, D=1024, H=16, Dstate=64
// ---------------------------------------------------------------------------

#define MAX_M 16384
#define NCH   4096
#define CHUNKS 64

// device-global scratch (no allocation allowed)
__device__ __half g_xnh[(size_t)MAX_M * 1024];   // xn (fp16), later "mixed" (fp16)
__device__ float  g_proj[(size_t)MAX_M * 4096];  // [gate(1024) | p(3072)] per token
__device__ __half g_wt1[(size_t)4096 * 1024];    // [Wg|Wp]^T  (N,K) K-major, fp16
__device__ __half g_wt2[(size_t)1024 * 1024];    // Wo^T       (N,K) K-major, fp16
__device__ float  g_cA[NCH * CHUNKS];
__device__ float  g_cB[NCH * CHUNKS];
__device__ float  g_hin[NCH * CHUNKS];

// ---------------------------------------------------------------------------
__device__ __forceinline__ void mma16(float* c,
                                      uint32_t a0, uint32_t a1, uint32_t a2, uint32_t a3,
                                      uint32_t b0, uint32_t b1) {
    asm volatile(
        "mma.sync.aligned.m16n8k16.row.col.f32.f16.f16.f32 "
        "{%0,%1,%2,%3},{%4,%5,%6,%7},{%8,%9},{%0,%1,%2,%3};"
        : "+f"(c[0]), "+f"(c[1]), "+f"(c[2]), "+f"(c[3])
        : "r"(a0), "r"(a1), "r"(a2), "r"(a3), "r"(b0), "r"(b1));
}
__device__ __forceinline__ void cpasync16(uint32_t saddr, const void* g) {
    asm volatile("cp.async.cg.shared.global [%0], [%1], 16;" :: "r"(saddr), "l"(g));
}
__device__ __forceinline__ float sigmoidf_(float v) {
    return 1.0f / (1.0f + __expf(-v));
}

// ---------------------------------------------------------------------------
// Transpose + convert all weights to fp16 [N,K] K-major.
// n: 0..1023 -> Wg cols, 1024..4095 -> Wp cols, 4096..5119 -> Wo cols
__global__ void transpose_weights(const float* __restrict__ Wg,
                                  const float* __restrict__ Wp,
                                  const float* __restrict__ Wo) {
    __shared__ float tile[32][33];
    const int kt = blockIdx.x, nt = blockIdx.y;
    const int x = threadIdx.x, y0 = threadIdx.y;
    #pragma unroll
    for (int yy = y0; yy < 32; yy += 8) {
        const int k = kt * 32 + yy;
        const int n = nt * 32 + x;
        float v;
        if (n < 1024)      v = Wg[(size_t)k * 1024 + n];
        else if (n < 4096) v = Wp[(size_t)k * 3072 + (n - 1024)];
        else               v = Wo[(size_t)k * 1024 + (n - 4096)];
        tile[yy][x] = v;
    }
    __syncthreads();
    #pragma unroll
    for (int yy = y0; yy < 32; yy += 8) {
        const int n = nt * 32 + yy;
        const int k = kt * 32 + x;
        const __half h = __float2half(tile[x][yy]);
        if (n < 4096) g_wt1[(size_t)n * 1024 + k] = h;
        else          g_wt2[(size_t)(n - 4096) * 1024 + k] = h;
    }
}

// ---------------------------------------------------------------------------
// RMSNorm -> fp16 xn (4 halfs per thread)
__global__ void rmsnorm_kernel(const float* __restrict__ x, const float* __restrict__ w) {
    const int row = blockIdx.x;
    const int tid = threadIdx.x;
    const float4* xr = (const float4*)(x + (size_t)row * 1024);
    float4 v = xr[tid];
    float ss = v.x * v.x + v.y * v.y + v.z * v.z + v.w * v.w;
    #pragma unroll
    for (int o = 16; o; o >>= 1) ss += __shfl_xor_sync(0xffffffff, ss, o);
    __shared__ float sred[8];
    const int lane = tid & 31, warp = tid >> 5;
    if (lane == 0) sred[warp] = ss;
    __syncthreads();
    if (warp == 0) {
        float t = sred[lane & 7];
        #pragma unroll
        for (int o = 4; o; o >>= 1) t += __shfl_xor_sync(0xffffffff, t, o);
        if (lane == 0) sred[0] = t;
    }
    __syncthreads();
    const float rinv = rsqrtf(sred[0] * (1.0f / 1024.0f) + 1e-6f);
    const float4 wv = ((const float4*)w)[tid];
    __half2 h01 = __floats2half2_rn(v.x * rinv * wv.x, v.y * rinv * wv.y);
    __half2 h23 = __floats2half2_rn(v.z * rinv * wv.z, v.w * rinv * wv.w);
    __half2* dst = (__half2*)(g_xnh + (size_t)row * 1024) + tid * 2;
    dst[0] = h01;
    dst[1] = h23;
}

// ---------------------------------------------------------------------------
// FP16 GEMM: CTA tile 128(M) x 128(N), BK=32 halfs, 256 threads.
// Warps 2(m) x 4(n), warp tile 64x32 (m16n8k16). Double-buffered cp.async.
// A smem [128][40] halfs, B smem [128 N][40] halfs (both K-major, pad 8).
// EPI==1: A=g_xnh, B=g_wt1, +bias, sigmoid on gate & delta cols -> g_proj.
// EPI==2: A=g_xnh(mixed), B=g_wt2, +bo + residual x -> d_out.
constexpr int HSTR  = 40;                 // smem row stride in halfs (80 B)
constexpr int HSTAGE = 128 * HSTR;        // halfs per stage tile (5120)

template<int EPI>
__global__ __launch_bounds__(256, 2)
void gemm_fp16(const float* __restrict__ bias0, const float* __restrict__ bias1,
               const float* __restrict__ resid, float* __restrict__ outp, int M) {
    __shared__ __half Asm[2][HSTAGE];
    __shared__ __half Bsm[2][HSTAGE];

    const int tid  = threadIdx.x;
    const int lane = tid & 31, warp = tid >> 5;
    const int wm = warp & 1, wn = warp >> 1;     // 2 x 4 warps
    const int bm = blockIdx.y, bn = blockIdx.x;

    const __half* __restrict__ Bw = (EPI == 1) ? g_wt1 : g_wt2;
    float* out = (EPI == 1) ? g_proj : outp;
    const int ldo = (EPI == 1) ? 4096 : 1024;

    // loaders: 128 rows x 4 chunks(16B) = 512 chunks each for A and B; 2/thread
    const int q0 = tid;            // chunk ids q0, q0+256
    const uint32_t sA = (uint32_t)__cvta_generic_to_shared(&Asm[0][0]);
    const uint32_t sB = (uint32_t)__cvta_generic_to_shared(&Bsm[0][0]);

    const __half* gA = g_xnh + (size_t)(bm * 128) * 1024;
    const __half* gB = Bw   + (size_t)(bn * 128) * 1024;

    float c[4][4][4];
    #pragma unroll
    for (int i = 0; i < 4; i++)
        #pragma unroll
        for (int j = 0; j < 4; j++)
            #pragma unroll
            for (int k = 0; k < 4; k++) c[i][j][k] = 0.0f;

    const int KT = 32;  // 1024 / 32

    #define LOAD_STAGE(s)                                                       \
    {                                                                           \
        const int _buf = (s) & 1;                                               \
        const int _kb  = (s) * 32;                                              \
        _Pragma("unroll")                                                       \
        for (int _i = 0; _i < 2; _i++) {                                        \
            const int _q = q0 + 256 * _i;                                       \
            const int _r = _q >> 2, _ch = _q & 3;                               \
            const uint32_t _off = (uint32_t)(_buf * HSTAGE + _r * HSTR + _ch * 8) * 2; \
            cpasync16(sA + _off, gA + (size_t)_r * 1024 + _kb + _ch * 8);       \
            cpasync16(sB + _off, gB + (size_t)_r * 1024 + _kb + _ch * 8);       \
        }                                                                       \
        asm volatile("cp.async.commit_group;");                                 \
    }

    LOAD_STAGE(0)

    for (int kt = 0; kt < KT; kt++) {
        if (kt + 1 < KT) LOAD_STAGE(kt + 1)
        asm volatile("cp.async.wait_group 1;");
        __syncthreads();

        const __half* Ab = &Asm[kt & 1][0];
        const __half* Bb = &Bsm[kt & 1][0];

        #pragma unroll
        for (int ks = 0; ks < 2; ks++) {       // two k16 steps per stage
            uint32_t af[4][4], bf[4][2];
            const int r0 = wm * 64 + (lane >> 2);
            const int cc = ks * 16 + (lane & 3) * 2;
            #pragma unroll
            for (int mt = 0; mt < 4; mt++) {
                const __half* ap = Ab + (r0 + mt * 16) * HSTR + cc;
                af[mt][0] = *(const uint32_t*)(ap);
                af[mt][1] = *(const uint32_t*)(ap + 8 * HSTR);
                af[mt][2] = *(const uint32_t*)(ap + 8);
                af[mt][3] = *(const uint32_t*)(ap + 8 * HSTR + 8);
            }
            const int n0 = wn * 32 + (lane >> 2);
            #pragma unroll
            for (int nt = 0; nt < 4; nt++) {
                const __half* bp2 = Bb + (n0 + nt * 8) * HSTR + cc;
                bf[nt][0] = *(const uint32_t*)(bp2);
                bf[nt][1] = *(const uint32_t*)(bp2 + 8);
            }
            #pragma unroll
            for (int mt = 0; mt < 4; mt++)
                #pragma unroll
                for (int nt = 0; nt < 4; nt++)
                    mma16(c[mt][nt], af[mt][0], af[mt][1], af[mt][2], af[mt][3],
                          bf[nt][0], bf[nt][1]);
        }
        __syncthreads();
    }
    #undef LOAD_STAGE

    // epilogue (accum layout: rows lane>>2 & +8; cols (lane&3)*2, +1)
    #pragma unroll
    for (int mt = 0; mt < 4; mt++) {
        const int rbase = bm * 128 + wm * 64 + mt * 16 + (lane >> 2);
        #pragma unroll
        for (int nt = 0; nt < 4; nt++) {
            const int col0 = bn * 128 + wn * 32 + nt * 8 + (lane & 3) * 2;
            float b0v, b1v;
            bool sg = false;
            if (EPI == 1) {
                if (col0 < 1024) { b0v = bias0[col0]; b1v = bias0[col0 + 1]; sg = true; }
                else {
                    b0v = bias1[col0 - 1024]; b1v = bias1[col0 - 1023];
                    sg = (((col0 - 1024) % 192) < 64);   // delta columns
                }
            } else {
                b0v = bias0[col0]; b1v = bias0[col0 + 1];
            }
            #pragma unroll
            for (int half_ = 0; half_ < 2; half_++) {
                const int row = rbase + 8 * half_;
                float v0 = c[mt][nt][2 * half_]     + b0v;
                float v1 = c[mt][nt][2 * half_ + 1] + b1v;
                if (EPI == 2) {
                    const float2 rr = *(const float2*)(resid + (size_t)row * 1024 + col0);
                    v0 += rr.x; v1 += rr.y;
                } else if (sg) {
                    v0 = sigmoidf_(v0); v1 = sigmoidf_(v1);
                }
                float2 st; st.x = v0; st.y = v1;
                *(float2*)(out + (size_t)row * ldo + col0) = st;
            }
        }
    }
}

// ---------------------------------------------------------------------------
// Chunked parallel scan (pass1/2 unchanged; pass3 reads/writes fp16 xn)
__global__ __launch_bounds__(256) void scan_pass1(int S, int L) {
    const int gid = blockIdx.x * blockDim.x + threadIdx.x;
    const int t = gid & (NCH - 1);
    const int c = gid >> 12;
    const int b  = t >> 10;
    const int hd = t & 1023;
    const int hh = hd >> 6;
    const int d  = hd & 63;
    const float* __restrict__ pd = g_proj + (size_t)b * S * 4096 + 1024 + hh * 192 + d
                                   + (size_t)c * L * 4096;
    float A = 1.0f, h = 0.0f;
    #pragma unroll 8
    for (int s = 0; s < L; s++) {
        const float dl = pd[(size_t)s * 4096];
        const float bv = pd[(size_t)s * 4096 + 64];
        A *= dl;
        h = fmaf(dl, h, bv);
    }
    g_cA[gid] = A;
    g_cB[gid] = h;
}

__global__ __launch_bounds__(256) void scan_pass2(const float* __restrict__ state0,
                                                  float* __restrict__ state_out, int C) {
    const int t = blockIdx.x * blockDim.x + threadIdx.x;
    float h = state0[t];
    #pragma unroll 8
    for (int c = 0; c < C; c++) {
        g_hin[c * NCH + t] = h;
        h = fmaf(g_cA[c * NCH + t], h, g_cB[c * NCH + t]);
    }
    if (state_out) state_out[t] = h;
}

__global__ __launch_bounds__(256) void scan_pass3(int S, int L) {
    const int gid = blockIdx.x * blockDim.x + threadIdx.x;
    const int t = gid & (NCH - 1);
    const int c = gid >> 12;
    const int b  = t >> 10;
    const int hd = t & 1023;
    const int hh = hd >> 6;
    const int d  = hd & 63;
    const size_t base = (size_t)b * S * 4096 + (size_t)c * L * 4096;
    const float* __restrict__ pd = g_proj + base + 1024 + hh * 192 + d;
    const float* __restrict__ pg = g_proj + base + hd;
    __half* __restrict__ xr = g_xnh + (size_t)b * S * 1024 + hd + (size_t)c * L * 1024;
    float h = g_hin[gid];
    #pragma unroll 4
    for (int s = 0; s < L; s++) {
        const float dl = pd[(size_t)s * 4096];
        const float bv = pd[(size_t)s * 4096 + 64];
        const float cv = pd[(size_t)s * 4096 + 128];
        const float g  = pg[(size_t)s * 4096];
        h = fmaf(dl, h, bv);
        const float ssm = cv * h;
        const float xv  = __half2float(xr[(size_t)s * 1024]);
        xr[(size_t)s * 1024] = __float2half(fmaf(g, ssm - xv, xv));
    }
}

// ---------------------------------------------------------------------------
extern "C" void kernel_launch(void* const* d_in, const int* in_sizes, int n_in,
                              void* d_out, int out_size) {
    const float* x      = (const float*)d_in[0];
    const float* state  = (const float*)d_in[1];
    const float* norm_w = (const float*)d_in[2];
    const float* Wp     = (const float*)d_in[3];
    const float* bp     = (const float*)d_in[4];
    const float* Wg     = (const float*)d_in[5];
    const float* bg     = (const float*)d_in[6];
    const float* Wo     = (const float*)d_in[7];
    const float* bo     = (const float*)d_in[8];
    float* out = (float*)d_out;

    const int M = in_sizes[0] / 1024;  // 16384
    const int S = M / 4;               // 4096
    const int L = S / CHUNKS;          // 64

    transpose_weights<<<dim3(32, 160), dim3(32, 8)>>>(Wg, Wp, Wo);
    rmsnorm_kernel<<<M, 256>>>(x, norm_w);

    gemm_fp16<1><<<dim3(32, M / 128), 256>>>(bg, bp, nullptr, nullptr, M);

    float* state_out = nullptr;
    if (out_size >= M * 1024 + 4096) state_out = out + (size_t)M * 1024;
    scan_pass1<<<NCH * CHUNKS / 256, 256>>>(S, L);
    scan_pass2<<<NCH / 256, 256>>>(state, state_out, CHUNKS);
    scan_pass3<<<NCH * CHUNKS / 256, 256>>>(S, L);

    gemm_fp16<2><<<dim3(8, M / 128), 256>>>(bo, nullptr, x, out, M);
}

// round 16
// speedup vs baseline: 1.9305x; 1.0586x over previous
#include <cuda_runtime.h>
#include <cuda_fp16.h>
#include <cstdint>

// ---------------------------------------------------------------------------
// MambaBlock: rmsnorm -> [gate|p] GEMM (fp16 mma.sync + ldmatrix) -> chunked
//             scan -> out GEMM.  Shapes: B=4, S=4096, D=1024, H=16, Dstate=64
// ---------------------------------------------------------------------------

#define MAX_M 16384
#define NCH   4096
#define CHUNKS 64

// device-global scratch (no allocation allowed)
__device__ __half g_xnh[(size_t)MAX_M * 1024];   // xn (fp16), later "mixed" (fp16)
__device__ float  g_proj[(size_t)MAX_M * 4096];  // [gate(1024) | p(3072)] per token
__device__ __half g_wt1[(size_t)4096 * 1024];    // [Wg|Wp]^T  (N,K) K-major, fp16
__device__ __half g_wt2[(size_t)1024 * 1024];    // Wo^T       (N,K) K-major, fp16
__device__ float  g_cA[NCH * CHUNKS];
__device__ float  g_cB[NCH * CHUNKS];
__device__ float  g_hin[NCH * CHUNKS];

// ---------------------------------------------------------------------------
__device__ __forceinline__ void mma16(float* c,
                                      uint32_t a0, uint32_t a1, uint32_t a2, uint32_t a3,
                                      uint32_t b0, uint32_t b1) {
    asm volatile(
        "mma.sync.aligned.m16n8k16.row.col.f32.f16.f16.f32 "
        "{%0,%1,%2,%3},{%4,%5,%6,%7},{%8,%9},{%0,%1,%2,%3};"
        : "+f"(c[0]), "+f"(c[1]), "+f"(c[2]), "+f"(c[3])
        : "r"(a0), "r"(a1), "r"(a2), "r"(a3), "r"(b0), "r"(b1));
}
__device__ __forceinline__ void ldmx4(uint32_t* r, uint32_t addr) {
    asm volatile("ldmatrix.sync.aligned.m8n8.x4.shared.b16 {%0,%1,%2,%3}, [%4];"
                 : "=r"(r[0]), "=r"(r[1]), "=r"(r[2]), "=r"(r[3]) : "r"(addr));
}
__device__ __forceinline__ void cpasync16(uint32_t saddr, const void* g) {
    asm volatile("cp.async.cg.shared.global [%0], [%1], 16;" :: "r"(saddr), "l"(g));
}
__device__ __forceinline__ float sigmoidf_(float v) {
    return 1.0f / (1.0f + __expf(-v));
}

// ---------------------------------------------------------------------------
// Transpose + convert all weights to fp16 [N,K] K-major.
__global__ void transpose_weights(const float* __restrict__ Wg,
                                  const float* __restrict__ Wp,
                                  const float* __restrict__ Wo) {
    __shared__ float tile[32][33];
    const int kt = blockIdx.x, nt = blockIdx.y;
    const int x = threadIdx.x, y0 = threadIdx.y;
    #pragma unroll
    for (int yy = y0; yy < 32; yy += 8) {
        const int k = kt * 32 + yy;
        const int n = nt * 32 + x;
        float v;
        if (n < 1024)      v = Wg[(size_t)k * 1024 + n];
        else if (n < 4096) v = Wp[(size_t)k * 3072 + (n - 1024)];
        else               v = Wo[(size_t)k * 1024 + (n - 4096)];
        tile[yy][x] = v;
    }
    __syncthreads();
    #pragma unroll
    for (int yy = y0; yy < 32; yy += 8) {
        const int n = nt * 32 + yy;
        const int k = kt * 32 + x;
        const __half h = __float2half(tile[x][yy]);
        if (n < 4096) g_wt1[(size_t)n * 1024 + k] = h;
        else          g_wt2[(size_t)(n - 4096) * 1024 + k] = h;
    }
}

// ---------------------------------------------------------------------------
// RMSNorm -> fp16 xn
__global__ void rmsnorm_kernel(const float* __restrict__ x, const float* __restrict__ w) {
    const int row = blockIdx.x;
    const int tid = threadIdx.x;
    const float4* xr = (const float4*)(x + (size_t)row * 1024);
    float4 v = xr[tid];
    float ss = v.x * v.x + v.y * v.y + v.z * v.z + v.w * v.w;
    #pragma unroll
    for (int o = 16; o; o >>= 1) ss += __shfl_xor_sync(0xffffffff, ss, o);
    __shared__ float sred[8];
    const int lane = tid & 31, warp = tid >> 5;
    if (lane == 0) sred[warp] = ss;
    __syncthreads();
    if (warp == 0) {
        float t = sred[lane & 7];
        #pragma unroll
        for (int o = 4; o; o >>= 1) t += __shfl_xor_sync(0xffffffff, t, o);
        if (lane == 0) sred[0] = t;
    }
    __syncthreads();
    const float rinv = rsqrtf(sred[0] * (1.0f / 1024.0f) + 1e-6f);
    const float4 wv = ((const float4*)w)[tid];
    __half2 h01 = __floats2half2_rn(v.x * rinv * wv.x, v.y * rinv * wv.y);
    __half2 h23 = __floats2half2_rn(v.z * rinv * wv.z, v.w * rinv * wv.w);
    __half2* dst = (__half2*)(g_xnh + (size_t)row * 1024) + tid * 2;
    dst[0] = h01;
    dst[1] = h23;
}

// ---------------------------------------------------------------------------
// FP16 GEMM: CTA tile 128x128, BK=32 halfs, 256 threads, warps 2(m)x4(n),
// warp tile 64x32. Fragments via ldmatrix.x4. Double-buffered cp.async.
constexpr int HSTR  = 40;                 // smem row stride in halfs (80 B)
constexpr int HSTAGE = 128 * HSTR;        // halfs per stage tile (5120)

template<int EPI>
__global__ __launch_bounds__(256, 2)
void gemm_fp16(const float* __restrict__ bias0, const float* __restrict__ bias1,
               const float* __restrict__ resid, float* __restrict__ outp, int M) {
    __shared__ __half Asm[2][HSTAGE];
    __shared__ __half Bsm[2][HSTAGE];

    const int tid  = threadIdx.x;
    const int lane = tid & 31, warp = tid >> 5;
    const int wm = warp & 1, wn = warp >> 1;     // 2 x 4 warps
    const int bm = blockIdx.y, bn = blockIdx.x;

    const __half* __restrict__ Bw = (EPI == 1) ? g_wt1 : g_wt2;
    float* out = (EPI == 1) ? g_proj : outp;
    const int ldo = (EPI == 1) ? 4096 : 1024;

    const int q0 = tid;
    const uint32_t sA = (uint32_t)__cvta_generic_to_shared(&Asm[0][0]);
    const uint32_t sB = (uint32_t)__cvta_generic_to_shared(&Bsm[0][0]);

    const __half* gA = g_xnh + (size_t)(bm * 128) * 1024;
    const __half* gB = Bw   + (size_t)(bn * 128) * 1024;

    // ldmatrix per-lane base addresses (bytes), stage 0, ks 0.
    // A x4 (per mt): lanes 0-15 rows 0-15 @k0, lanes 16-31 rows 0-15 @k8.
    uint32_t aAddr[4];
    {
        const int r_in  = lane & 15;
        const int khalf = (lane >> 4) & 1;
        #pragma unroll
        for (int mt = 0; mt < 4; mt++)
            aAddr[mt] = sA + (uint32_t)(((wm * 64 + mt * 16 + r_in) * HSTR
                                         + khalf * 8) * 2);
    }
    // B x4 (per pair p): group=lane>>3: (nt = 2p + (g>>1)) rows, khalf = g&1.
    uint32_t bAddr[2];
    {
        const int g  = lane >> 3;
        const int rr = lane & 7;
        #pragma unroll
        for (int p = 0; p < 2; p++)
            bAddr[p] = sB + (uint32_t)(((wn * 32 + (2 * p + (g >> 1)) * 8 + rr) * HSTR
                                        + (g & 1) * 8) * 2);
    }

    float c[4][4][4];
    #pragma unroll
    for (int i = 0; i < 4; i++)
        #pragma unroll
        for (int j = 0; j < 4; j++)
            #pragma unroll
            for (int k = 0; k < 4; k++) c[i][j][k] = 0.0f;

    const int KT = 32;  // 1024 / 32

    #define LOAD_STAGE(s)                                                       \
    {                                                                           \
        const int _buf = (s) & 1;                                               \
        const int _kb  = (s) * 32;                                              \
        _Pragma("unroll")                                                       \
        for (int _i = 0; _i < 2; _i++) {                                        \
            const int _q = q0 + 256 * _i;                                       \
            const int _r = _q >> 2, _ch = _q & 3;                               \
            const uint32_t _off = (uint32_t)(_buf * HSTAGE + _r * HSTR + _ch * 8) * 2; \
            cpasync16(sA + _off, gA + (size_t)_r * 1024 + _kb + _ch * 8);       \
            cpasync16(sB + _off, gB + (size_t)_r * 1024 + _kb + _ch * 8);       \
        }                                                                       \
        asm volatile("cp.async.commit_group;");                                 \
    }

    LOAD_STAGE(0)

    for (int kt = 0; kt < KT; kt++) {
        if (kt + 1 < KT) LOAD_STAGE(kt + 1)
        asm volatile("cp.async.wait_group 1;");
        __syncthreads();

        const uint32_t stOff = (uint32_t)((kt & 1) * HSTAGE * 2);

        #pragma unroll
        for (int ks = 0; ks < 2; ks++) {       // two k16 steps per stage
            const uint32_t kOff = stOff + ks * 32;   // 16 halfs
            uint32_t af[4][4], bq[2][4];
            #pragma unroll
            for (int mt = 0; mt < 4; mt++) ldmx4(af[mt], aAddr[mt] + kOff);
            #pragma unroll
            for (int p = 0; p < 2; p++)     ldmx4(bq[p], bAddr[p] + kOff);

            // bq[p] = { bf[2p][0], bf[2p][1], bf[2p+1][0], bf[2p+1][1] }
            #pragma unroll
            for (int mt = 0; mt < 4; mt++) {
                #pragma unroll
                for (int nt = 0; nt < 4; nt++) {
                    const uint32_t b0 = bq[nt >> 1][(nt & 1) * 2 + 0];
                    const uint32_t b1 = bq[nt >> 1][(nt & 1) * 2 + 1];
                    mma16(c[mt][nt], af[mt][0], af[mt][1], af[mt][2], af[mt][3],
                          b0, b1);
                }
            }
        }
        __syncthreads();
    }
    #undef LOAD_STAGE

    // epilogue (accum layout: rows lane>>2 & +8; cols (lane&3)*2, +1)
    #pragma unroll
    for (int mt = 0; mt < 4; mt++) {
        const int rbase = bm * 128 + wm * 64 + mt * 16 + (lane >> 2);
        #pragma unroll
        for (int nt = 0; nt < 4; nt++) {
            const int col0 = bn * 128 + wn * 32 + nt * 8 + (lane & 3) * 2;
            float b0v, b1v;
            bool sg = false;
            if (EPI == 1) {
                if (col0 < 1024) { b0v = bias0[col0]; b1v = bias0[col0 + 1]; sg = true; }
                else {
                    b0v = bias1[col0 - 1024]; b1v = bias1[col0 - 1023];
                    sg = (((col0 - 1024) % 192) < 64);   // delta columns
                }
            } else {
                b0v = bias0[col0]; b1v = bias0[col0 + 1];
            }
            #pragma unroll
            for (int half_ = 0; half_ < 2; half_++) {
                const int row = rbase + 8 * half_;
                float v0 = c[mt][nt][2 * half_]     + b0v;
                float v1 = c[mt][nt][2 * half_ + 1] + b1v;
                if (EPI == 2) {
                    const float2 rr = *(const float2*)(resid + (size_t)row * 1024 + col0);
                    v0 += rr.x; v1 += rr.y;
                } else if (sg) {
                    v0 = sigmoidf_(v0); v1 = sigmoidf_(v1);
                }
                float2 st; st.x = v0; st.y = v1;
                *(float2*)(out + (size_t)row * ldo + col0) = st;
            }
        }
    }
}

// ---------------------------------------------------------------------------
// Chunked parallel scan (verified 5.1 TB/s)
__global__ __launch_bounds__(256) void scan_pass1(int S, int L) {
    const int gid = blockIdx.x * blockDim.x + threadIdx.x;
    const int t = gid & (NCH - 1);
    const int c = gid >> 12;
    const int b  = t >> 10;
    const int hd = t & 1023;
    const int hh = hd >> 6;
    const int d  = hd & 63;
    const float* __restrict__ pd = g_proj + (size_t)b * S * 4096 + 1024 + hh * 192 + d
                                   + (size_t)c * L * 4096;
    float A = 1.0f, h = 0.0f;
    #pragma unroll 8
    for (int s = 0; s < L; s++) {
        const float dl = pd[(size_t)s * 4096];
        const float bv = pd[(size_t)s * 4096 + 64];
        A *= dl;
        h = fmaf(dl, h, bv);
    }
    g_cA[gid] = A;
    g_cB[gid] = h;
}

__global__ __launch_bounds__(256) void scan_pass2(const float* __restrict__ state0,
                                                  float* __restrict__ state_out, int C) {
    const int t = blockIdx.x * blockDim.x + threadIdx.x;
    float h = state0[t];
    #pragma unroll 8
    for (int c = 0; c < C; c++) {
        g_hin[c * NCH + t] = h;
        h = fmaf(g_cA[c * NCH + t], h, g_cB[c * NCH + t]);
    }
    if (state_out) state_out[t] = h;
}

__global__ __launch_bounds__(256) void scan_pass3(int S, int L) {
    const int gid = blockIdx.x * blockDim.x + threadIdx.x;
    const int t = gid & (NCH - 1);
    const int c = gid >> 12;
    const int b  = t >> 10;
    const int hd = t & 1023;
    const int hh = hd >> 6;
    const int d  = hd & 63;
    const size_t base = (size_t)b * S * 4096 + (size_t)c * L * 4096;
    const float* __restrict__ pd = g_proj + base + 1024 + hh * 192 + d;
    const float* __restrict__ pg = g_proj + base + hd;
    __half* __restrict__ xr = g_xnh + (size_t)b * S * 1024 + hd + (size_t)c * L * 1024;
    float h = g_hin[gid];
    #pragma unroll 4
    for (int s = 0; s < L; s++) {
        const float dl = pd[(size_t)s * 4096];
        const float bv = pd[(size_t)s * 4096 + 64];
        const float cv = pd[(size_t)s * 4096 + 128];
        const float g  = pg[(size_t)s * 4096];
        h = fmaf(dl, h, bv);
        const float ssm = cv * h;
        const float xv  = __half2float(xr[(size_t)s * 1024]);
        xr[(size_t)s * 1024] = __float2half(fmaf(g, ssm - xv, xv));
    }
}

// ---------------------------------------------------------------------------
extern "C" void kernel_launch(void* const* d_in, const int* in_sizes, int n_in,
                              void* d_out, int out_size) {
    const float* x      = (const float*)d_in[0];
    const float* state  = (const float*)d_in[1];
    const float* norm_w = (const float*)d_in[2];
    const float* Wp     = (const float*)d_in[3];
    const float* bp     = (const float*)d_in[4];
    const float* Wg     = (const float*)d_in[5];
    const float* bg     = (const float*)d_in[6];
    const float* Wo     = (const float*)d_in[7];
    const float* bo     = (const float*)d_in[8];
    float* out = (float*)d_out;

    const int M = in_sizes[0] / 1024;  // 16384
    const int S = M / 4;               // 4096
    const int L = S / CHUNKS;          // 64

    transpose_weights<<<dim3(32, 160), dim3(32, 8)>>>(Wg, Wp, Wo);
    rmsnorm_kernel<<<M, 256>>>(x, norm_w);

    gemm_fp16<1><<<dim3(32, M / 128), 256>>>(bg, bp, nullptr, nullptr, M);

    float* state_out = nullptr;
    if (out_size >= M * 1024 + 4096) state_out = out + (size_t)M * 1024;
    scan_pass1<<<NCH * CHUNKS / 256, 256>>>(S, L);
    scan_pass2<<<NCH / 256, 256>>>(state, state_out, CHUNKS);
    scan_pass3<<<NCH * CHUNKS / 256, 256>>>(S, L);

    gemm_fp16<2><<<dim3(8, M / 128), 256>>>(bo, nullptr, x, out, M);
}